// round 2
// baseline (speedup 1.0000x reference)
#include <cuda_runtime.h>
#include <cstdint>

// KGAT fused 2-layer kernel.
// Per node n (one CTA):
//   hd[k] = W2 @ dst[k]            (once, shared by both layers)
//   c1[k]=<hd,rel>, c2[k]=||hd||^2, r2[k]=||rel||^2  (once)
//   per layer: hs = W1 @ src + b; s2=||hs||^2
//     e[k] = leakyrelu( (c1+<hs,rel>) / (max(sqrt(s2+2<hs,hd>+c2),eps)*max(sqrt(r2),eps)) )
//     att = masked softmax; out = att @ dst + src
// Layer 2 uses layer-1 output as src. dst/rel/hd/c* live in smem.

#define D 64
#define KNB 64
#define PAD 68      // padded row stride (floats), 16B-aligned, conflict-friendly

typedef unsigned long long ull;

__device__ __forceinline__ ull pack2(float a, float b) {
    ull r;
    asm("mov.b64 %0, {%1, %2};" : "=l"(r) : "r"(__float_as_uint(a)), "r"(__float_as_uint(b)));
    return r;
}
__device__ __forceinline__ ull fma2(ull a, ull b, ull c) {
    ull d;
    asm("fma.rn.f32x2 %0, %1, %2, %3;" : "=l"(d) : "l"(a), "l"(b), "l"(c));
    return d;
}
__device__ __forceinline__ void unpack2(ull v, float& lo, float& hi) {
    unsigned int l, h;
    asm("mov.b64 {%0, %1}, %2;" : "=r"(l), "=r"(h) : "l"(v));
    lo = __uint_as_float(l); hi = __uint_as_float(h);
}
__device__ __forceinline__ float getc(const float4& v, int i) {
    return (i == 0) ? v.x : (i == 1) ? v.y : (i == 2) ? v.z : v.w;
}

__global__ void __launch_bounds__(256, 2) kgat_kernel(
    const float* __restrict__ src_embs,
    const float* __restrict__ dst_embs,
    const float* __restrict__ rel_embs,
    const float* __restrict__ fc_w,     // [D, 2D] row-major
    const float* __restrict__ fc_b,     // [D]
    const int*   __restrict__ mask,     // [N, K]
    float* __restrict__ out)            // [N, D]
{
    extern __shared__ float smem[];
    float* sWt  = smem;                  // [2D][PAD]  transposed W: sWt[f*PAD+d] = fc_w[d*128+f]
    float* sdst = sWt  + 128 * PAD;      // [K][PAD]
    float* srel = sdst + KNB * PAD;      // [K][PAD]
    float* shd  = srel + KNB * PAD;      // [K][PAD]

    __shared__ float ssrc[D], shs[D], sb[D];
    __shared__ float sc1[KNB], sc2[KNB], sr2[KNB];
    __shared__ float sdr[KNB], sdh[KNB], satt[KNB];
    __shared__ float s_s2;

    const int n = blockIdx.x;
    const int t = threadIdx.x;

    const float* gdst = dst_embs + (size_t)n * (KNB * D);
    const float* grel = rel_embs + (size_t)n * (KNB * D);
    const int*   gmask = mask + (size_t)n * KNB;

    // ---- loads: dst/rel (float4, coalesced), W transposed, src, bias ----
    for (int i = t; i < KNB * D / 4; i += 256) {
        int k = i >> 4, c = (i & 15) << 2;
        float4 dv = ((const float4*)gdst)[i];
        float4 rv = ((const float4*)grel)[i];
        *(float4*)&sdst[k * PAD + c] = dv;
        *(float4*)&srel[k * PAD + c] = rv;
    }
    for (int i = t; i < D * 2 * D; i += 256) {
        int d = i >> 7, f = i & 127;
        sWt[f * PAD + d] = fc_w[i];
    }
    if (t < D) {
        ssrc[t] = src_embs[(size_t)n * D + t];
        sb[t] = fc_b[t];
    }
    __syncthreads();

    // ---- HD GEMM: hd[k][d] = sum_f dst[k][f] * W[d][64+f]  (f32x2 packed FFMA) ----
    {
        const int tk = t >> 4, td = t & 15;
        const int k0 = tk << 2, d0 = td << 2;
        ull acc0[4], acc1[4];
#pragma unroll
        for (int j = 0; j < 4; j++) { acc0[j] = 0ull; acc1[j] = 0ull; }

#pragma unroll 4
        for (int fb = 0; fb < D; fb += 4) {
            float4 dv0 = *(const float4*)&sdst[(k0 + 0) * PAD + fb];
            float4 dv1 = *(const float4*)&sdst[(k0 + 1) * PAD + fb];
            float4 dv2 = *(const float4*)&sdst[(k0 + 2) * PAD + fb];
            float4 dv3 = *(const float4*)&sdst[(k0 + 3) * PAD + fb];
#pragma unroll
            for (int ff = 0; ff < 4; ff++) {
                const float4 wv = *(const float4*)&sWt[(D + fb + ff) * PAD + d0];
                ull wlo = pack2(wv.x, wv.y);
                ull whi = pack2(wv.z, wv.w);
                ull s0 = pack2(getc(dv0, ff), getc(dv0, ff));
                ull s1 = pack2(getc(dv1, ff), getc(dv1, ff));
                ull s2p = pack2(getc(dv2, ff), getc(dv2, ff));
                ull s3 = pack2(getc(dv3, ff), getc(dv3, ff));
                acc0[0] = fma2(s0, wlo, acc0[0]); acc1[0] = fma2(s0, whi, acc1[0]);
                acc0[1] = fma2(s1, wlo, acc0[1]); acc1[1] = fma2(s1, whi, acc1[1]);
                acc0[2] = fma2(s2p, wlo, acc0[2]); acc1[2] = fma2(s2p, whi, acc1[2]);
                acc0[3] = fma2(s3, wlo, acc0[3]); acc1[3] = fma2(s3, whi, acc1[3]);
            }
        }
#pragma unroll
        for (int j = 0; j < 4; j++) {
            float4 o;
            unpack2(acc0[j], o.x, o.y);
            unpack2(acc1[j], o.z, o.w);
            *(float4*)&shd[(k0 + j) * PAD + d0] = o;
        }
    }
    __syncthreads();

    // ---- per-k precompute: c1 = <hd,rel>, c2 = ||hd||^2, r2 = ||rel||^2 ----
    {
        const int w = t >> 5, l = t & 31;
#pragma unroll
        for (int j = 0; j < 8; j++) {
            int k = (w << 3) + j;
            float a0 = shd[k * PAD + l],      a1 = shd[k * PAD + 32 + l];
            float r0 = srel[k * PAD + l],     r1 = srel[k * PAD + 32 + l];
            float c1v = a0 * r0 + a1 * r1;
            float c2v = a0 * a0 + a1 * a1;
            float r2v = r0 * r0 + r1 * r1;
#pragma unroll
            for (int s = 16; s; s >>= 1) {
                c1v += __shfl_xor_sync(0xffffffffu, c1v, s);
                c2v += __shfl_xor_sync(0xffffffffu, c2v, s);
                r2v += __shfl_xor_sync(0xffffffffu, r2v, s);
            }
            if (l == 0) { sc1[k] = c1v; sc2[k] = c2v; sr2[k] = r2v; }
        }
    }

    // ---- two GAT layers ----
    for (int layer = 0; layer < 2; layer++) {
        __syncthreads();
        // hs = W1 @ src + b
        if (t < D) {
            float acc = sb[t];
#pragma unroll 8
            for (int f = 0; f < D; f++)
                acc = fmaf(ssrc[f], sWt[f * PAD + t], acc);
            shs[t] = acc;
        }
        __syncthreads();
        // s2 = ||hs||^2  (warp 0)
        if (t < 32) {
            float v = shs[t] * shs[t] + shs[t + 32] * shs[t + 32];
#pragma unroll
            for (int s = 16; s; s >>= 1) v += __shfl_xor_sync(0xffffffffu, v, s);
            if (t == 0) s_s2 = v;
        }
        // dot_hr[k]=<hs,rel[k]>, dot_hh[k]=<hs,hd[k]>  (all warps)
        {
            const int w = t >> 5, l = t & 31;
            float h0 = shs[l], h1 = shs[l + 32];
#pragma unroll
            for (int j = 0; j < 8; j++) {
                int k = (w << 3) + j;
                float dr = h0 * srel[k * PAD + l] + h1 * srel[k * PAD + 32 + l];
                float dh = h0 * shd[k * PAD + l]  + h1 * shd[k * PAD + 32 + l];
#pragma unroll
                for (int s = 16; s; s >>= 1) {
                    dr += __shfl_xor_sync(0xffffffffu, dr, s);
                    dh += __shfl_xor_sync(0xffffffffu, dh, s);
                }
                if (l == 0) { sdr[k] = dr; sdh[k] = dh; }
            }
        }
        __syncthreads();
        // e[k] -> masked logits
        if (t < KNB) {
            float num = sc1[t] + sdr[t];
            float hn2 = s_s2 + 2.0f * sdh[t] + sc2[t];
            float hn = sqrtf(fmaxf(hn2, 0.0f));
            float rn = sqrtf(sr2[t]);
            float den = fmaxf(hn, 1e-8f) * fmaxf(rn, 1e-8f);
            float e = num / den;
            e = (e < 0.0f) ? 0.2f * e : e;
            satt[t] = (gmask[t] > 0) ? e : -9e15f;
        }
        __syncthreads();
        // softmax over K (warp 0)
        if (t < 32) {
            float e0 = satt[t], e1 = satt[t + 32];
            float m = fmaxf(e0, e1);
#pragma unroll
            for (int s = 16; s; s >>= 1) m = fmaxf(m, __shfl_xor_sync(0xffffffffu, m, s));
            float x0 = __expf(e0 - m), x1 = __expf(e1 - m);
            float sum = x0 + x1;
#pragma unroll
            for (int s = 16; s; s >>= 1) sum += __shfl_xor_sync(0xffffffffu, sum, s);
            float inv = 1.0f / sum;
            satt[t] = x0 * inv; satt[t + 32] = x1 * inv;
        }
        __syncthreads();
        // agg = att @ dst, + residual
        if (t < D) {
            float a = 0.0f;
#pragma unroll 8
            for (int k = 0; k < KNB; k++)
                a = fmaf(satt[k], sdst[k * PAD + t], a);
            float o = a + ssrc[t];
            if (layer == 0) ssrc[t] = o;               // becomes src of layer 2
            else out[(size_t)n * D + t] = o;
        }
    }
}

static const int SMEM_BYTES = (128 * PAD + 3 * KNB * PAD) * (int)sizeof(float);  // 87040

extern "C" void kernel_launch(void* const* d_in, const int* in_sizes, int n_in,
                              void* d_out, int out_size) {
    const float* src  = (const float*)d_in[0];
    const float* dst  = (const float*)d_in[1];
    const float* rel  = (const float*)d_in[2];
    const float* fcw  = (const float*)d_in[3];
    const float* fcb  = (const float*)d_in[4];
    const int*   mask = (const int*)d_in[5];
    (void)n_in;

    int N = in_sizes[0] / D;   // 50000
    float* outp = (float*)d_out;
    (void)out_size;

    cudaFuncSetAttribute(kgat_kernel, cudaFuncAttributeMaxDynamicSharedMemorySize, SMEM_BYTES);
    kgat_kernel<<<N, 256, SMEM_BYTES>>>(src, dst, rel, fcw, fcb, mask, outp);
}

// round 3
// speedup vs baseline: 1.3770x; 1.3770x over previous
#include <cuda_runtime.h>
#include <cstdint>

// KGAT fused 2-layer kernel, v2.
// Key identities:
//   h = hs + hd,  hd[k] = W2 @ dst[k]
//   <h,rel>   = <hs,rel> + c1[k],          c1[k] = <hd[k],rel[k]>
//   ||h||^2   = ||hs||^2 + 2<g,dst[k]> + c2[k],  g = W2^T hs,  c2[k] = ||hd[k]||^2
// => hd never stored; GEMM epilogue reduces c1,c2 in registers.

#define D 64
#define KNB 64
#define PAD 68

typedef unsigned long long ull;

__device__ float g_Wt[128 * PAD];   // transposed, padded W: g_Wt[f*PAD+d] = fc_w[d*128+f]

__device__ __forceinline__ ull pack2(float a, float b) {
    ull r;
    asm("mov.b64 %0, {%1, %2};" : "=l"(r) : "r"(__float_as_uint(a)), "r"(__float_as_uint(b)));
    return r;
}
__device__ __forceinline__ ull fma2(ull a, ull b, ull c) {
    ull d;
    asm("fma.rn.f32x2 %0, %1, %2, %3;" : "=l"(d) : "l"(a), "l"(b), "l"(c));
    return d;
}
__device__ __forceinline__ void unpack2(ull v, float& lo, float& hi) {
    unsigned int l, h;
    asm("mov.b64 {%0, %1}, %2;" : "=r"(l), "=r"(h) : "l"(v));
    lo = __uint_as_float(l); hi = __uint_as_float(h);
}
__device__ __forceinline__ float getc(const float4& v, int i) {
    return (i == 0) ? v.x : (i == 1) ? v.y : (i == 2) ? v.z : v.w;
}
__device__ __forceinline__ float dot4(const float4& a, const float4& b) {
    return a.x * b.x + a.y * b.y + a.z * b.z + a.w * b.w;
}

__global__ void transpose_w_kernel(const float* __restrict__ fc_w) {
    int i = blockIdx.x * 256 + threadIdx.x;
    if (i < D * 2 * D) {
        int d = i >> 7, f = i & 127;
        g_Wt[f * PAD + d] = fc_w[i];
    }
}

__global__ void __launch_bounds__(256, 3) kgat_kernel(
    const float* __restrict__ src_embs,
    const float* __restrict__ dst_embs,
    const float* __restrict__ rel_embs,
    const float* __restrict__ fc_b,
    const int*   __restrict__ mask,
    float* __restrict__ out)
{
    extern __shared__ float smem[];
    float* sWt  = smem;                  // [128][PAD]
    float* sdst = sWt  + 128 * PAD;      // [K][PAD]
    float* srel = sdst + KNB * PAD;      // [K][PAD]

    __shared__ float ssrc[D], shs[D], sg[D], sb[D];
    __shared__ float sc1[KNB], sc2[KNB], sr2[KNB];
    __shared__ float sdr[KNB], sdh[KNB], satt[KNB];
    __shared__ int   smask[KNB];
    __shared__ float s_s2;

    const int n = blockIdx.x;
    const int t = threadIdx.x;

    const float* gdst = dst_embs + (size_t)n * (KNB * D);
    const float* grel = rel_embs + (size_t)n * (KNB * D);

    // ---- loads: W (pre-transposed, conflict-free copy), dst/rel, src, bias, mask ----
    for (int i = t; i < 128 * (PAD / 4); i += 256)
        ((float4*)sWt)[i] = ((const float4*)g_Wt)[i];
    for (int i = t; i < KNB * D / 4; i += 256) {
        int k = i >> 4, c = (i & 15) << 2;
        *(float4*)&sdst[k * PAD + c] = ((const float4*)gdst)[i];
        *(float4*)&srel[k * PAD + c] = ((const float4*)grel)[i];
    }
    if (t < D) {
        ssrc[t] = src_embs[(size_t)n * D + t];
        sb[t] = fc_b[t];
        smask[t] = mask[(size_t)n * KNB + t];
    }
    __syncthreads();

    // ---- r2[k] = ||rel[k]||^2 : row-per-quad float4 dots ----
    {
        const int k = t >> 2, q = t & 3;
        float v = 0.0f;
#pragma unroll
        for (int j = 0; j < 4; j++) {
            float4 rv = *(const float4*)&srel[k * PAD + q * 16 + 4 * j];
            v += dot4(rv, rv);
        }
        v += __shfl_xor_sync(0xffffffffu, v, 1);
        v += __shfl_xor_sync(0xffffffffu, v, 2);
        if (q == 0) sr2[k] = v;
    }

    // ---- HD GEMM (f32x2) with fused c1/c2 epilogue ----
    {
        const int tk = t >> 4, td = t & 15;
        const int k0 = tk << 2, d0 = td << 2;
        ull acc0[4], acc1[4];
#pragma unroll
        for (int j = 0; j < 4; j++) { acc0[j] = 0ull; acc1[j] = 0ull; }

#pragma unroll 4
        for (int fb = 0; fb < D; fb += 4) {
            float4 dv0 = *(const float4*)&sdst[(k0 + 0) * PAD + fb];
            float4 dv1 = *(const float4*)&sdst[(k0 + 1) * PAD + fb];
            float4 dv2 = *(const float4*)&sdst[(k0 + 2) * PAD + fb];
            float4 dv3 = *(const float4*)&sdst[(k0 + 3) * PAD + fb];
#pragma unroll
            for (int ff = 0; ff < 4; ff++) {
                const float4 wv = *(const float4*)&sWt[(D + fb + ff) * PAD + d0];
                ull wlo = pack2(wv.x, wv.y);
                ull whi = pack2(wv.z, wv.w);
                ull s0 = pack2(getc(dv0, ff), getc(dv0, ff));
                ull s1 = pack2(getc(dv1, ff), getc(dv1, ff));
                ull s2p = pack2(getc(dv2, ff), getc(dv2, ff));
                ull s3 = pack2(getc(dv3, ff), getc(dv3, ff));
                acc0[0] = fma2(s0, wlo, acc0[0]); acc1[0] = fma2(s0, whi, acc1[0]);
                acc0[1] = fma2(s1, wlo, acc0[1]); acc1[1] = fma2(s1, whi, acc1[1]);
                acc0[2] = fma2(s2p, wlo, acc0[2]); acc1[2] = fma2(s2p, whi, acc1[2]);
                acc0[3] = fma2(s3, wlo, acc0[3]); acc1[3] = fma2(s3, whi, acc1[3]);
            }
        }
        // epilogue: partial c1/c2 over this thread's 4x4 hd tile, reduce across 16 td lanes
        float c1p[4], c2p[4];
#pragma unroll
        for (int j = 0; j < 4; j++) {
            float4 o;
            unpack2(acc0[j], o.x, o.y);
            unpack2(acc1[j], o.z, o.w);
            float4 rv = *(const float4*)&srel[(k0 + j) * PAD + d0];
            c1p[j] = dot4(o, rv);
            c2p[j] = dot4(o, o);
        }
#pragma unroll
        for (int s = 1; s < 16; s <<= 1) {
#pragma unroll
            for (int j = 0; j < 4; j++) {
                c1p[j] += __shfl_xor_sync(0xffffffffu, c1p[j], s);
                c2p[j] += __shfl_xor_sync(0xffffffffu, c2p[j], s);
            }
        }
        if (td == 0) {
#pragma unroll
            for (int j = 0; j < 4; j++) { sc1[k0 + j] = c1p[j]; sc2[k0 + j] = c2p[j]; }
        }
    }

    // ---- two GAT layers ----
    for (int layer = 0; layer < 2; layer++) {
        __syncthreads();
        // hs = W1 @ src + b  (column access, ILP-4)
        if (t < D) {
            float a0 = 0.f, a1 = 0.f, a2 = 0.f, a3 = 0.f;
#pragma unroll
            for (int f = 0; f < D; f += 4) {
                a0 = fmaf(ssrc[f + 0], sWt[(f + 0) * PAD + t], a0);
                a1 = fmaf(ssrc[f + 1], sWt[(f + 1) * PAD + t], a1);
                a2 = fmaf(ssrc[f + 2], sWt[(f + 2) * PAD + t], a2);
                a3 = fmaf(ssrc[f + 3], sWt[(f + 3) * PAD + t], a3);
            }
            shs[t] = ((a0 + a1) + (a2 + a3)) + sb[t];
        }
        __syncthreads();
        // g = W2^T @ hs  (row access, float4)  [threads 0..63]
        if (t < D) {
            const float* row = &sWt[(D + t) * PAD];
            float a0 = 0.f, a1 = 0.f;
#pragma unroll
            for (int dd = 0; dd < D; dd += 8) {
                float4 w0 = *(const float4*)&row[dd];
                float4 w1 = *(const float4*)&row[dd + 4];
                float4 h0 = *(const float4*)&shs[dd];
                float4 h1 = *(const float4*)&shs[dd + 4];
                a0 += dot4(w0, h0);
                a1 += dot4(w1, h1);
            }
            sg[t] = a0 + a1;
        }
        // s2 = ||hs||^2  [warp 2]
        if (t >= 64 && t < 96) {
            int l = t - 64;
            float v = shs[l] * shs[l] + shs[l + 32] * shs[l + 32];
#pragma unroll
            for (int s = 16; s; s >>= 1) v += __shfl_xor_sync(0xffffffffu, v, s);
            if (l == 0) s_s2 = v;
        }
        __syncthreads();
        // dr[k]=<hs,rel[k]>, dh[k]=<g,dst[k]>  (row-per-quad)
        {
            const int k = t >> 2, q = t & 3;
            float dr = 0.f, dh = 0.f;
#pragma unroll
            for (int j = 0; j < 4; j++) {
                int c = q * 16 + 4 * j;
                float4 hv = *(const float4*)&shs[c];
                float4 gv = *(const float4*)&sg[c];
                float4 rv = *(const float4*)&srel[k * PAD + c];
                float4 dv = *(const float4*)&sdst[k * PAD + c];
                dr += dot4(hv, rv);
                dh += dot4(gv, dv);
            }
            dr += __shfl_xor_sync(0xffffffffu, dr, 1);
            dh += __shfl_xor_sync(0xffffffffu, dh, 1);
            dr += __shfl_xor_sync(0xffffffffu, dr, 2);
            dh += __shfl_xor_sync(0xffffffffu, dh, 2);
            if (q == 0) { sdr[k] = dr; sdh[k] = dh; }
        }
        __syncthreads();
        // logits + masked softmax  [warp 0]
        if (t < 32) {
            float e[2];
#pragma unroll
            for (int h = 0; h < 2; h++) {
                int k = t + 32 * h;
                float num = sc1[k] + sdr[k];
                float hn2 = s_s2 + 2.0f * sdh[k] + sc2[k];
                float hn = sqrtf(fmaxf(hn2, 0.0f));
                float rn = sqrtf(sr2[k]);
                float den = fmaxf(hn, 1e-8f) * fmaxf(rn, 1e-8f);
                float ee = num / den;
                ee = (ee < 0.0f) ? 0.2f * ee : ee;
                e[h] = (smask[k] > 0) ? ee : -9e15f;
            }
            float m = fmaxf(e[0], e[1]);
#pragma unroll
            for (int s = 16; s; s >>= 1) m = fmaxf(m, __shfl_xor_sync(0xffffffffu, m, s));
            float x0 = __expf(e[0] - m), x1 = __expf(e[1] - m);
            float sum = x0 + x1;
#pragma unroll
            for (int s = 16; s; s >>= 1) sum += __shfl_xor_sync(0xffffffffu, sum, s);
            float inv = 1.0f / sum;
            satt[t] = x0 * inv; satt[t + 32] = x1 * inv;
        }
        __syncthreads();
        // agg = att @ dst + residual
        if (t < D) {
            float a0 = 0.f, a1 = 0.f, a2 = 0.f, a3 = 0.f;
#pragma unroll
            for (int k = 0; k < KNB; k += 4) {
                a0 = fmaf(satt[k + 0], sdst[(k + 0) * PAD + t], a0);
                a1 = fmaf(satt[k + 1], sdst[(k + 1) * PAD + t], a1);
                a2 = fmaf(satt[k + 2], sdst[(k + 2) * PAD + t], a2);
                a3 = fmaf(satt[k + 3], sdst[(k + 3) * PAD + t], a3);
            }
            float o = ((a0 + a1) + (a2 + a3)) + ssrc[t];
            if (layer == 0) ssrc[t] = o;
            else out[(size_t)n * D + t] = o;
        }
    }
}

static const int SMEM_BYTES = (128 * PAD + 2 * KNB * PAD) * (int)sizeof(float);  // 69632

extern "C" void kernel_launch(void* const* d_in, const int* in_sizes, int n_in,
                              void* d_out, int out_size) {
    const float* src  = (const float*)d_in[0];
    const float* dst  = (const float*)d_in[1];
    const float* rel  = (const float*)d_in[2];
    const float* fcw  = (const float*)d_in[3];
    const float* fcb  = (const float*)d_in[4];
    const int*   mask = (const int*)d_in[5];
    (void)n_in;

    int N = in_sizes[0] / D;   // 50000
    float* outp = (float*)d_out;
    (void)out_size;

    transpose_w_kernel<<<(D * 2 * D + 255) / 256, 256>>>(fcw);

    cudaFuncSetAttribute(kgat_kernel, cudaFuncAttributeMaxDynamicSharedMemorySize, SMEM_BYTES);
    kgat_kernel<<<N, 256, SMEM_BYTES>>>(src, dst, rel, fcb, mask, outp);
}